// round 6
// baseline (speedup 1.0000x reference)
#include <cuda_runtime.h>
#include <cuda_fp16.h>
#include <math.h>
#include <stdint.h>
#include <mma.h>

using namespace nvcuda;

// Problem constants: B=2, S=2048 -> T=4096 tokens, H=1024, E=8, K=2, FF=4096
#define TT   4096
#define HH   1024
#define EE   8
#define FFD  4096
#define RTOT (TT*2)
#define LN_EPS 1e-5f

// ---------------------------------------------------------------------------
// Scratch
// ---------------------------------------------------------------------------
__device__ __half g_h[RTOT * HH];                    // 16.8 MB
__device__ __half g_act[(long long)RTOT * FFD];      // 67 MB
__device__ float  g_y[RTOT * HH];                    // 33.5 MB
__device__ float  g_stat[TT * 2];                    // mu, rsig per token
__device__ int    g_cnt[EE];
__device__ int    g_off[EE + 1];
__device__ int    g_slot_e[RTOT];
__device__ int    g_slot_pos[RTOT];
__device__ int    g_slot_row[RTOT];
__device__ float  g_slot_w[RTOT];

// ---------------------------------------------------------------------------
// Helpers
// ---------------------------------------------------------------------------
__device__ __forceinline__ uint32_t smem_u32(const void* p) {
    uint32_t a;
    asm("{ .reg .u64 t; cvta.to.shared.u64 t, %1; cvt.u32.u64 %0, t; }" : "=r"(a) : "l"(p));
    return a;
}
#define CP16(dst, src) \
    asm volatile("cp.async.cg.shared.global [%0], [%1], 16;" :: "r"(dst), "l"(src))
#define CP_COMMIT() asm volatile("cp.async.commit_group;" ::: "memory")
#define CP_WAIT0()  asm volatile("cp.async.wait_group 0;" ::: "memory")

// ---------------------------------------------------------------------------
// Kernel 0: zero counters
// ---------------------------------------------------------------------------
__global__ void k_zero() { if (threadIdx.x < EE) g_cnt[threadIdx.x] = 0; }

// ---------------------------------------------------------------------------
// Kernel 1: router + LN stats. Thread owns 4 columns x all 8 experts.
// ---------------------------------------------------------------------------
__global__ void __launch_bounds__(256) k_router_ln(
    const float* __restrict__ x, const float* __restrict__ rW, const float* __restrict__ rb)
{
    __shared__ float red[10][8];
    __shared__ float fin[10];

    const int t = blockIdx.x, tid = threadIdx.x;
    const int wid = tid >> 5, lane = tid & 31;

    const float4 xv = ((const float4*)(x + (long long)t * HH))[tid];
    float s  = xv.x + xv.y + xv.z + xv.w;
    float s2 = xv.x * xv.x + xv.y * xv.y + xv.z * xv.z + xv.w * xv.w;

    float acc[8];
    #pragma unroll
    for (int e = 0; e < 8; e++) acc[e] = 0.f;
    const float xj[4] = { xv.x, xv.y, xv.z, xv.w };
    #pragma unroll
    for (int j = 0; j < 4; j++) {
        const float4* wr = (const float4*)(rW + (size_t)(tid * 4 + j) * EE);
        float4 w0 = wr[0], w1 = wr[1];
        acc[0] = fmaf(xj[j], w0.x, acc[0]); acc[1] = fmaf(xj[j], w0.y, acc[1]);
        acc[2] = fmaf(xj[j], w0.z, acc[2]); acc[3] = fmaf(xj[j], w0.w, acc[3]);
        acc[4] = fmaf(xj[j], w1.x, acc[4]); acc[5] = fmaf(xj[j], w1.y, acc[5]);
        acc[6] = fmaf(xj[j], w1.z, acc[6]); acc[7] = fmaf(xj[j], w1.w, acc[7]);
    }

    #pragma unroll
    for (int o = 16; o; o >>= 1) {
        s  += __shfl_down_sync(0xFFFFFFFFu, s, o);
        s2 += __shfl_down_sync(0xFFFFFFFFu, s2, o);
        #pragma unroll
        for (int e = 0; e < 8; e++) acc[e] += __shfl_down_sync(0xFFFFFFFFu, acc[e], o);
    }
    if (lane == 0) {
        red[0][wid] = s; red[1][wid] = s2;
        #pragma unroll
        for (int e = 0; e < 8; e++) red[2 + e][wid] = acc[e];
    }
    __syncthreads();
    if (tid < 10) {
        float v = 0.f;
        #pragma unroll
        for (int i = 0; i < 8; i++) v += red[tid][i];
        fin[tid] = v;
    }
    __syncthreads();

    if (tid == 0) {
        float mu = fin[0] / (float)HH;
        g_stat[t * 2 + 0] = mu;
        g_stat[t * 2 + 1] = rsqrtf(fin[1] / (float)HH - mu * mu + LN_EPS);

        float lg[8];
        #pragma unroll
        for (int e = 0; e < 8; e++) lg[e] = fin[2 + e] + rb[e];
        int e0 = 0;
        #pragma unroll
        for (int e = 1; e < EE; e++) if (lg[e] > lg[e0]) e0 = e;
        int e1 = (e0 == 0) ? 1 : 0;
        #pragma unroll
        for (int e = 0; e < EE; e++) { if (e == e0) continue; if (lg[e] > lg[e1]) e1 = e; }
        float p1 = expf(lg[e1] - lg[e0]);
        float inv = 1.f / (1.f + p1);
        int   es[2] = { e0, e1 };
        float ws[2] = { inv, p1 * inv };
        #pragma unroll
        for (int k = 0; k < 2; k++) {
            int e = es[k];
            int pos = atomicAdd(&g_cnt[e], 1);
            g_slot_e[t * 2 + k] = e; g_slot_pos[t * 2 + k] = pos; g_slot_w[t * 2 + k] = ws[k];
        }
    }
}

__global__ void k_prefix() {
    if (threadIdx.x == 0) {
        int a = 0;
        #pragma unroll
        for (int e = 0; e < EE; e++) { g_off[e] = a; a += g_cnt[e]; }
        g_off[EE] = a;
    }
}

// ---------------------------------------------------------------------------
// Kernel 3: slot -> row + h[row] = ((x[tok]-mu)*rsig * ln_g[e] + ln_b[e]) fp16
// One block per slot.
// ---------------------------------------------------------------------------
__global__ void __launch_bounds__(256) k_build_h(
    const float* __restrict__ x,
    const float* __restrict__ lng, const float* __restrict__ lnb)
{
    const int i   = blockIdx.x;                 // slot
    const int e   = g_slot_e[i];
    const int row = g_off[e] + g_slot_pos[i];
    if (threadIdx.x == 0) g_slot_row[i] = row;
    const int tok = i >> 1;
    const float mu  = g_stat[tok * 2 + 0];
    const float rsg = g_stat[tok * 2 + 1];
    const float* xr = x + (long long)tok * HH;
    const float* gg = lng + (long long)e * HH;
    const float* bb = lnb + (long long)e * HH;
    __half* o = g_h + (long long)row * HH;
    const int c = threadIdx.x * 4;
    float4 xv = *(const float4*)(xr + c);
    float4 gv = *(const float4*)(gg + c);
    float4 bv = *(const float4*)(bb + c);
    float h0 = fmaf((xv.x - mu) * rsg, gv.x, bv.x);
    float h1 = fmaf((xv.y - mu) * rsg, gv.y, bv.y);
    float h2 = fmaf((xv.z - mu) * rsg, gv.z, bv.z);
    float h3 = fmaf((xv.w - mu) * rsg, gv.w, bv.w);
    __half2 p0 = __floats2half2_rn(h0, h1);
    __half2 p1 = __floats2half2_rn(h2, h3);
    *(uint2*)(o + c) = make_uint2(*(uint32_t*)&p0, *(uint32_t*)&p1);
}

// ---------------------------------------------------------------------------
// fp16 wmma grouped GEMM with in-kernel fp32->fp16 weight conversion.
// BM=128, BN=128, BK=64, 256 threads (8 warps 4x2), warp tile 32x64.
// A (fp16 acts): cp.async double-buffered. B (fp32 weights): LDG->cvt->STS,
// register-prefetched one stage ahead.
// FIRST: A=g_h[rows,1024] B=W1[e][1024,4096] fp32 -> gelu(.+b1) -> g_act fp16
// else : A=g_act[rows,4096] B=W2[e][4096,1024] fp32 -> g_y fp32
// ---------------------------------------------------------------------------
#define A_LDMH 72
#define B_LDMH 136
#define A_STH (128 * A_LDMH)    // 9216 halfs / stage
#define B_STH (64 * B_LDMH)     // 8704 halfs / stage
#define GEMM_SMEM_BYTES ((2 * A_STH + 2 * B_STH) * 2)   // 71680
#define OUT_LDM 132

template <bool FIRST>
__global__ void __launch_bounds__(256) k_gemm_h(
    const float* __restrict__ Wmat, const float* __restrict__ bias)
{
    constexpr int KD  = FIRST ? HH : FFD;
    constexpr int ND  = FIRST ? FFD : HH;
    constexpr int NIT = KD / 64;

    const int e    = blockIdx.z;
    const int r0   = g_off[e];
    const int rows = g_off[e + 1] - r0;
    const int row0 = blockIdx.y * 128;
    if (row0 >= rows) return;
    const int n0 = blockIdx.x * 128;

    extern __shared__ __align__(16) char smraw[];
    __half* sm = (__half*)smraw;
    const uint32_t sbase = smem_u32(sm);

    const int tid = threadIdx.x;
    const int w   = tid >> 5;
    const int wm  = w >> 1;     // 0..3
    const int wn  = w & 1;      // 0..1

    const __half* A  = FIRST ? g_h : g_act;
    const float*  Bg = Wmat + (size_t)e * KD * ND;

    wmma::fragment<wmma::accumulator, 16, 16, 16, float> acc[2][4];
    #pragma unroll
    for (int i = 0; i < 2; i++)
        #pragma unroll
        for (int j = 0; j < 4; j++) wmma::fill_fragment(acc[i][j], 0.f);

    // B loader: thread -> k-row bk = tid>>2 (0..63), 32 n at bn0=(tid&3)*32
    const int bk  = tid >> 2;
    const int bn0 = (tid & 3) * 32;
    const float* Bth = Bg + (size_t)bk * ND + n0 + bn0;

    uint32_t bh[16];   // 32 halfs (one stage worth per thread)
    auto ldg_b = [&](int it) {
        const float4* src = (const float4*)(Bth + (size_t)it * 64 * ND);
        #pragma unroll
        for (int p = 0; p < 8; p++) {
            float4 v = src[p];
            __half2 h0 = __floats2half2_rn(v.x, v.y);
            __half2 h1 = __floats2half2_rn(v.z, v.w);
            bh[2 * p]     = *(uint32_t*)&h0;
            bh[2 * p + 1] = *(uint32_t*)&h1;
        }
    };
    auto sts_b = [&](int buf) {
        uint32_t base = sbase + (uint32_t)(2 * A_STH + buf * B_STH + bk * B_LDMH + bn0) * 2u;
        #pragma unroll
        for (int g = 0; g < 4; g++)
            asm volatile("st.shared.v4.b32 [%0], {%1,%2,%3,%4};"
                :: "r"(base + g * 16u),
                   "r"(bh[4 * g + 0]), "r"(bh[4 * g + 1]),
                   "r"(bh[4 * g + 2]), "r"(bh[4 * g + 3]));
    };
    auto cpa_a = [&](int it, int buf) {
        const int k0 = it * 64;
        #pragma unroll
        for (int j = 0; j < 4; j++) {
            int idx = tid + 256 * j;
            int r = idx >> 3, kc = (idx & 7) * 8;
            int arow = row0 + r; if (arow >= rows) arow = rows - 1;
            const __half* src = A + (size_t)(r0 + arow) * KD + k0 + kc;
            uint32_t dst = sbase + (uint32_t)(buf * A_STH + r * A_LDMH + kc) * 2u;
            CP16(dst, src);
        }
        CP_COMMIT();
    };

    ldg_b(0);
    cpa_a(0, 0);

    for (int it = 0; it < NIT; ++it) {
        const int buf = it & 1;
        sts_b(buf);
        CP_WAIT0();           // A(it) resident
        __syncthreads();

        if (it + 1 < NIT) {
            ldg_b(it + 1);
            cpa_a(it + 1, buf ^ 1);
        }

        const __half* pA = sm + buf * A_STH;
        const __half* pB = sm + 2 * A_STH + buf * B_STH;

        #pragma unroll
        for (int ks = 0; ks < 4; ks++) {
            wmma::fragment<wmma::matrix_a, 16, 16, 16, __half, wmma::row_major> af[2];
            wmma::fragment<wmma::matrix_b, 16, 16, 16, __half, wmma::row_major> bf[4];
            #pragma unroll
            for (int i = 0; i < 2; i++)
                wmma::load_matrix_sync(af[i], pA + (wm * 32 + i * 16) * A_LDMH + ks * 16, A_LDMH);
            #pragma unroll
            for (int j = 0; j < 4; j++)
                wmma::load_matrix_sync(bf[j], pB + (ks * 16) * B_LDMH + wn * 64 + j * 16, B_LDMH);
            #pragma unroll
            for (int i = 0; i < 2; i++)
                #pragma unroll
                for (int j = 0; j < 4; j++)
                    wmma::mma_sync(acc[i][j], af[i], bf[j], acc[i][j]);
        }
        __syncthreads();
    }

    // Epilogue via smem fp32 (guarded; partial m-tiles stay inside segment)
    float* smf = (float*)smraw;
    #pragma unroll
    for (int i = 0; i < 2; i++)
        #pragma unroll
        for (int j = 0; j < 4; j++)
            wmma::store_matrix_sync(
                smf + (size_t)(wm * 32 + i * 16) * OUT_LDM + wn * 64 + j * 16,
                acc[i][j], OUT_LDM, wmma::mem_row_major);
    __syncthreads();

    const int col = (tid & 31) * 4;
    const float* brow = FIRST ? (bias + (size_t)e * ND + n0) : (const float*)0;
    #pragma unroll
    for (int rr = 0; rr < 16; rr++) {
        int r = (tid >> 5) + rr * 8;
        int m = row0 + r;
        if (m < rows) {
            const float* so = smf + (size_t)r * OUT_LDM + col;
            float v0 = so[0], v1 = so[1], v2 = so[2], v3 = so[3];
            if (FIRST) {
                float4 bv = *(const float4*)(brow + col);
                v0 += bv.x; v1 += bv.y; v2 += bv.z; v3 += bv.w;
                v0 = 0.5f * v0 * (1.0f + erff(v0 * 0.70710678118654752f));
                v1 = 0.5f * v1 * (1.0f + erff(v1 * 0.70710678118654752f));
                v2 = 0.5f * v2 * (1.0f + erff(v2 * 0.70710678118654752f));
                v3 = 0.5f * v3 * (1.0f + erff(v3 * 0.70710678118654752f));
                __half2 p0 = __floats2half2_rn(v0, v1);
                __half2 p1 = __floats2half2_rn(v2, v3);
                *(uint2*)(g_act + (size_t)(r0 + m) * ND + n0 + col) =
                    make_uint2(*(uint32_t*)&p0, *(uint32_t*)&p1);
            } else {
                *(float4*)(g_y + (size_t)(r0 + m) * ND + n0 + col) =
                    make_float4(v0, v1, v2, v3);
            }
        }
    }
}

// ---------------------------------------------------------------------------
// Combine: out = x + w0*(y0 + b2[e0]) + w1*(y1 + b2[e1])
// ---------------------------------------------------------------------------
__global__ void __launch_bounds__(256) k_combine(
    const float* __restrict__ x, const float* __restrict__ b2, float* __restrict__ out)
{
    const int t = blockIdx.x;
    const int r0 = g_slot_row[t * 2 + 0], r1 = g_slot_row[t * 2 + 1];
    const int e0 = g_slot_e[t * 2 + 0],  e1 = g_slot_e[t * 2 + 1];
    const float w0 = g_slot_w[t * 2 + 0], w1 = g_slot_w[t * 2 + 1];
    const float* y0 = g_y + (long long)r0 * HH;
    const float* y1 = g_y + (long long)r1 * HH;
    const float* bb0 = b2 + (long long)e0 * HH;
    const float* bb1 = b2 + (long long)e1 * HH;
    const float* xr = x + (long long)t * HH;
    float* o = out + (long long)t * HH;
    const int c = threadIdx.x * 4;
    float4 xv = *(const float4*)(xr + c);
    float4 a0 = *(const float4*)(y0 + c);
    float4 a1 = *(const float4*)(y1 + c);
    float4 c0 = *(const float4*)(bb0 + c);
    float4 c1 = *(const float4*)(bb1 + c);
    float4 r;
    r.x = xv.x + w0 * (a0.x + c0.x) + w1 * (a1.x + c1.x);
    r.y = xv.y + w0 * (a0.y + c0.y) + w1 * (a1.y + c1.y);
    r.z = xv.z + w0 * (a0.z + c0.z) + w1 * (a1.z + c1.z);
    r.w = xv.w + w0 * (a0.w + c0.w) + w1 * (a1.w + c1.w);
    *(float4*)(o + c) = r;
}

// ---------------------------------------------------------------------------
// Launch
// ---------------------------------------------------------------------------
extern "C" void kernel_launch(void* const* d_in, const int* in_sizes, int n_in,
                              void* d_out, int out_size)
{
    const float* x   = (const float*)d_in[0];
    const float* rW  = (const float*)d_in[1];
    const float* rb  = (const float*)d_in[2];
    const float* lng = (const float*)d_in[3];
    const float* lnb = (const float*)d_in[4];
    const float* W1  = (const float*)d_in[5];
    const float* b1  = (const float*)d_in[6];
    const float* W2  = (const float*)d_in[7];
    const float* b2  = (const float*)d_in[8];
    float* out = (float*)d_out;

    cudaFuncSetAttribute(k_gemm_h<true>,  cudaFuncAttributeMaxDynamicSharedMemorySize, GEMM_SMEM_BYTES);
    cudaFuncSetAttribute(k_gemm_h<false>, cudaFuncAttributeMaxDynamicSharedMemorySize, GEMM_SMEM_BYTES);

    k_zero<<<1, 32>>>();
    k_router_ln<<<TT, 256>>>(x, rW, rb);
    k_prefix<<<1, 32>>>();
    k_build_h<<<RTOT, 256>>>(x, lng, lnb);

    dim3 g1(FFD / 128, RTOT / 128, EE);   // 32 x 64 x 8 (most m-tiles exit early)
    k_gemm_h<true><<<g1, 256, GEMM_SMEM_BYTES>>>(W1, b1);

    dim3 g2(HH / 128, RTOT / 128, EE);    // 8 x 64 x 8
    k_gemm_h<false><<<g2, 256, GEMM_SMEM_BYTES>>>(W2, nullptr);

    k_combine<<<TT, 256>>>(x, b2, out);
}

// round 7
// speedup vs baseline: 1.4970x; 1.4970x over previous
#include <cuda_runtime.h>
#include <cuda_fp16.h>
#include <math.h>
#include <stdint.h>
#include <mma.h>

using namespace nvcuda;

// Problem constants: B=2, S=2048 -> T=4096 tokens, H=1024, E=8, K=2, FF=4096
#define TT   4096
#define HH   1024
#define EE   8
#define FFD  4096
#define RTOT (TT*2)
#define LN_EPS 1e-5f
#define W1N  (EE * HH * FFD)   // 33.5M
#define W2N  (EE * FFD * HH)

// ---------------------------------------------------------------------------
// Scratch
// ---------------------------------------------------------------------------
__device__ __half g_h[RTOT * HH];                    // 16.8 MB
__device__ __half g_act[(long long)RTOT * FFD];      // 67 MB
__device__ float  g_y[RTOT * HH];                    // 33.5 MB
__device__ __half g_W1h[W1N];                        // 67 MB
__device__ __half g_W2h[W2N];                        // 67 MB
__device__ float  g_stat[TT * 2];                    // mu, rsig per token
__device__ int    g_cnt[EE];
__device__ int    g_off[EE + 1];
__device__ int    g_slot_e[RTOT];
__device__ int    g_slot_pos[RTOT];
__device__ int    g_slot_row[RTOT];
__device__ float  g_slot_w[RTOT];

// ---------------------------------------------------------------------------
// Helpers
// ---------------------------------------------------------------------------
__device__ __forceinline__ uint32_t smem_u32(const void* p) {
    uint32_t a;
    asm("{ .reg .u64 t; cvta.to.shared.u64 t, %1; cvt.u32.u64 %0, t; }" : "=r"(a) : "l"(p));
    return a;
}
#define CP16(dst, src) \
    asm volatile("cp.async.cg.shared.global [%0], [%1], 16;" :: "r"(dst), "l"(src))
#define CP_COMMIT() asm volatile("cp.async.commit_group;" ::: "memory")
#define CP_WAIT0()  asm volatile("cp.async.wait_group 0;" ::: "memory")
#define CP_WAIT1()  asm volatile("cp.async.wait_group 1;" ::: "memory")

// ---------------------------------------------------------------------------
// Weight conversion fp32 -> fp16 (bandwidth-bound; runs every launch)
// ---------------------------------------------------------------------------
__global__ void __launch_bounds__(256) k_f2h(const float* __restrict__ src,
                                            __half* __restrict__ dst, int n) {
    int i = (blockIdx.x * 256 + threadIdx.x) * 4;
    for (; i < n; i += gridDim.x * 1024) {
        float4 v = *(const float4*)(src + i);
        __half2 a = __floats2half2_rn(v.x, v.y);
        __half2 b = __floats2half2_rn(v.z, v.w);
        *(uint2*)(dst + i) = make_uint2(*(uint32_t*)&a, *(uint32_t*)&b);
    }
}

// ---------------------------------------------------------------------------
// Kernel 0: zero counters
// ---------------------------------------------------------------------------
__global__ void k_zero() { if (threadIdx.x < EE) g_cnt[threadIdx.x] = 0; }

// ---------------------------------------------------------------------------
// Kernel 1: router + LN stats. Thread owns 4 columns x all 8 experts.
// ---------------------------------------------------------------------------
__global__ void __launch_bounds__(256) k_router_ln(
    const float* __restrict__ x, const float* __restrict__ rW, const float* __restrict__ rb)
{
    __shared__ float red[10][8];
    __shared__ float fin[10];

    const int t = blockIdx.x, tid = threadIdx.x;
    const int wid = tid >> 5, lane = tid & 31;

    const float4 xv = ((const float4*)(x + (long long)t * HH))[tid];
    float s  = xv.x + xv.y + xv.z + xv.w;
    float s2 = xv.x * xv.x + xv.y * xv.y + xv.z * xv.z + xv.w * xv.w;

    float acc[8];
    #pragma unroll
    for (int e = 0; e < 8; e++) acc[e] = 0.f;
    const float xj[4] = { xv.x, xv.y, xv.z, xv.w };
    #pragma unroll
    for (int j = 0; j < 4; j++) {
        const float4* wr = (const float4*)(rW + (size_t)(tid * 4 + j) * EE);
        float4 w0 = wr[0], w1 = wr[1];
        acc[0] = fmaf(xj[j], w0.x, acc[0]); acc[1] = fmaf(xj[j], w0.y, acc[1]);
        acc[2] = fmaf(xj[j], w0.z, acc[2]); acc[3] = fmaf(xj[j], w0.w, acc[3]);
        acc[4] = fmaf(xj[j], w1.x, acc[4]); acc[5] = fmaf(xj[j], w1.y, acc[5]);
        acc[6] = fmaf(xj[j], w1.z, acc[6]); acc[7] = fmaf(xj[j], w1.w, acc[7]);
    }

    #pragma unroll
    for (int o = 16; o; o >>= 1) {
        s  += __shfl_down_sync(0xFFFFFFFFu, s, o);
        s2 += __shfl_down_sync(0xFFFFFFFFu, s2, o);
        #pragma unroll
        for (int e = 0; e < 8; e++) acc[e] += __shfl_down_sync(0xFFFFFFFFu, acc[e], o);
    }
    if (lane == 0) {
        red[0][wid] = s; red[1][wid] = s2;
        #pragma unroll
        for (int e = 0; e < 8; e++) red[2 + e][wid] = acc[e];
    }
    __syncthreads();
    if (tid < 10) {
        float v = 0.f;
        #pragma unroll
        for (int i = 0; i < 8; i++) v += red[tid][i];
        fin[tid] = v;
    }
    __syncthreads();

    if (tid == 0) {
        float mu = fin[0] / (float)HH;
        g_stat[t * 2 + 0] = mu;
        g_stat[t * 2 + 1] = rsqrtf(fin[1] / (float)HH - mu * mu + LN_EPS);

        float lg[8];
        #pragma unroll
        for (int e = 0; e < 8; e++) lg[e] = fin[2 + e] + rb[e];
        int e0 = 0;
        #pragma unroll
        for (int e = 1; e < EE; e++) if (lg[e] > lg[e0]) e0 = e;
        int e1 = (e0 == 0) ? 1 : 0;
        #pragma unroll
        for (int e = 0; e < EE; e++) { if (e == e0) continue; if (lg[e] > lg[e1]) e1 = e; }
        float p1 = expf(lg[e1] - lg[e0]);
        float inv = 1.f / (1.f + p1);
        int   es[2] = { e0, e1 };
        float ws[2] = { inv, p1 * inv };
        #pragma unroll
        for (int k = 0; k < 2; k++) {
            int e = es[k];
            int pos = atomicAdd(&g_cnt[e], 1);
            g_slot_e[t * 2 + k] = e; g_slot_pos[t * 2 + k] = pos; g_slot_w[t * 2 + k] = ws[k];
        }
    }
}

__global__ void k_prefix() {
    if (threadIdx.x == 0) {
        int a = 0;
        #pragma unroll
        for (int e = 0; e < EE; e++) { g_off[e] = a; a += g_cnt[e]; }
        g_off[EE] = a;
    }
}

// ---------------------------------------------------------------------------
// Kernel 3: slot -> row + h[row] = ((x[tok]-mu)*rsig * ln_g[e] + ln_b[e]) fp16
// ---------------------------------------------------------------------------
__global__ void __launch_bounds__(256) k_build_h(
    const float* __restrict__ x,
    const float* __restrict__ lng, const float* __restrict__ lnb)
{
    const int i   = blockIdx.x;                 // slot
    const int e   = g_slot_e[i];
    const int row = g_off[e] + g_slot_pos[i];
    if (threadIdx.x == 0) g_slot_row[i] = row;
    const int tok = i >> 1;
    const float mu  = g_stat[tok * 2 + 0];
    const float rsg = g_stat[tok * 2 + 1];
    const float* xr = x + (long long)tok * HH;
    const float* gg = lng + (long long)e * HH;
    const float* bb = lnb + (long long)e * HH;
    __half* o = g_h + (long long)row * HH;
    const int c = threadIdx.x * 4;
    float4 xv = *(const float4*)(xr + c);
    float4 gv = *(const float4*)(gg + c);
    float4 bv = *(const float4*)(bb + c);
    float h0 = fmaf((xv.x - mu) * rsg, gv.x, bv.x);
    float h1 = fmaf((xv.y - mu) * rsg, gv.y, bv.y);
    float h2 = fmaf((xv.z - mu) * rsg, gv.z, bv.z);
    float h3 = fmaf((xv.w - mu) * rsg, gv.w, bv.w);
    __half2 p0 = __floats2half2_rn(h0, h1);
    __half2 p1 = __floats2half2_rn(h2, h3);
    *(uint2*)(o + c) = make_uint2(*(uint32_t*)&p0, *(uint32_t*)&p1);
}

// ---------------------------------------------------------------------------
// fp16 wmma grouped GEMM (R5-validated): BM=128, BN=128, BK=64, 256 threads,
// warp tile 32x64 (2x4 m16n16k16, fp32 acc), all-cp.async double-buffered.
// FIRST: A=g_h[rows,1024] B=g_W1h[e][1024,4096] -> gelu(.+b1) -> g_act (fp16)
// else : A=g_act[rows,4096] B=g_W2h[e][4096,1024] -> g_y (fp32)
// ---------------------------------------------------------------------------
#define A_LDMH 72
#define B_LDMH 136
#define A_STH (128 * A_LDMH)    // 9216 halfs / stage
#define B_STH (64 * B_LDMH)     // 8704 halfs / stage
#define GEMM_SMEM_BYTES ((2 * A_STH + 2 * B_STH) * 2)   // 71680
#define OUT_LDM 132

template <bool FIRST>
__global__ void __launch_bounds__(256) k_gemm_h(
    const __half* __restrict__ Wh, const float* __restrict__ bias)
{
    constexpr int KD  = FIRST ? HH : FFD;
    constexpr int ND  = FIRST ? FFD : HH;
    constexpr int NIT = KD / 64;

    const int e    = blockIdx.z;
    const int r0   = g_off[e];
    const int rows = g_off[e + 1] - r0;
    const int row0 = blockIdx.y * 128;
    if (row0 >= rows) return;
    const int n0 = blockIdx.x * 128;

    extern __shared__ __align__(16) char smraw[];
    __half* sm = (__half*)smraw;
    const uint32_t sbase = smem_u32(sm);

    const int tid = threadIdx.x;
    const int w   = tid >> 5;
    const int wm  = w >> 1;     // 0..3
    const int wn  = w & 1;      // 0..1

    const __half* A  = FIRST ? g_h : g_act;
    const __half* Bg = Wh + (size_t)e * KD * ND;

    wmma::fragment<wmma::accumulator, 16, 16, 16, float> acc[2][4];
    #pragma unroll
    for (int i = 0; i < 2; i++)
        #pragma unroll
        for (int j = 0; j < 4; j++) wmma::fill_fragment(acc[i][j], 0.f);

    auto load_stage = [&](int it, int buf) {
        const int k0 = it * 64;
        #pragma unroll
        for (int j = 0; j < 4; j++) {
            int idx = tid + 256 * j;
            int r = idx >> 3, kc = (idx & 7) * 8;
            int arow = row0 + r; if (arow >= rows) arow = rows - 1;
            const __half* src = A + (size_t)(r0 + arow) * KD + k0 + kc;
            uint32_t dst = sbase + (uint32_t)(buf * A_STH + r * A_LDMH + kc) * 2u;
            CP16(dst, src);
        }
        #pragma unroll
        for (int j = 0; j < 4; j++) {
            int idx = tid + 256 * j;
            int kk = idx >> 4, nc = (idx & 15) * 8;
            const __half* src = Bg + (size_t)(k0 + kk) * ND + n0 + nc;
            uint32_t dst = sbase + (uint32_t)(2 * A_STH + buf * B_STH + kk * B_LDMH + nc) * 2u;
            CP16(dst, src);
        }
        CP_COMMIT();
    };

    load_stage(0, 0);

    for (int it = 0; it < NIT; ++it) {
        if (it + 1 < NIT) { load_stage(it + 1, (it + 1) & 1); CP_WAIT1(); }
        else              { CP_WAIT0(); }
        __syncthreads();

        const __half* pA = sm + (it & 1) * A_STH;
        const __half* pB = sm + 2 * A_STH + (it & 1) * B_STH;

        #pragma unroll
        for (int ks = 0; ks < 4; ks++) {
            wmma::fragment<wmma::matrix_a, 16, 16, 16, __half, wmma::row_major> af[2];
            wmma::fragment<wmma::matrix_b, 16, 16, 16, __half, wmma::row_major> bf[4];
            #pragma unroll
            for (int i = 0; i < 2; i++)
                wmma::load_matrix_sync(af[i], pA + (wm * 32 + i * 16) * A_LDMH + ks * 16, A_LDMH);
            #pragma unroll
            for (int j = 0; j < 4; j++)
                wmma::load_matrix_sync(bf[j], pB + (ks * 16) * B_LDMH + wn * 64 + j * 16, B_LDMH);
            #pragma unroll
            for (int i = 0; i < 2; i++)
                #pragma unroll
                for (int j = 0; j < 4; j++)
                    wmma::mma_sync(acc[i][j], af[i], bf[j], acc[i][j]);
        }
        __syncthreads();
    }

    // Epilogue via smem fp32 (guarded; partial m-tiles stay inside segment)
    float* smf = (float*)smraw;
    #pragma unroll
    for (int i = 0; i < 2; i++)
        #pragma unroll
        for (int j = 0; j < 4; j++)
            wmma::store_matrix_sync(
                smf + (size_t)(wm * 32 + i * 16) * OUT_LDM + wn * 64 + j * 16,
                acc[i][j], OUT_LDM, wmma::mem_row_major);
    __syncthreads();

    const int col = (tid & 31) * 4;
    const float* brow = FIRST ? (bias + (size_t)e * ND + n0) : (const float*)0;
    #pragma unroll
    for (int rr = 0; rr < 16; rr++) {
        int r = (tid >> 5) + rr * 8;
        int m = row0 + r;
        if (m < rows) {
            const float* so = smf + (size_t)r * OUT_LDM + col;
            float v0 = so[0], v1 = so[1], v2 = so[2], v3 = so[3];
            if (FIRST) {
                float4 bv = *(const float4*)(brow + col);
                v0 += bv.x; v1 += bv.y; v2 += bv.z; v3 += bv.w;
                v0 = 0.5f * v0 * (1.0f + erff(v0 * 0.70710678118654752f));
                v1 = 0.5f * v1 * (1.0f + erff(v1 * 0.70710678118654752f));
                v2 = 0.5f * v2 * (1.0f + erff(v2 * 0.70710678118654752f));
                v3 = 0.5f * v3 * (1.0f + erff(v3 * 0.70710678118654752f));
                __half2 p0 = __floats2half2_rn(v0, v1);
                __half2 p1 = __floats2half2_rn(v2, v3);
                *(uint2*)(g_act + (size_t)(r0 + m) * ND + n0 + col) =
                    make_uint2(*(uint32_t*)&p0, *(uint32_t*)&p1);
            } else {
                *(float4*)(g_y + (size_t)(r0 + m) * ND + n0 + col) =
                    make_float4(v0, v1, v2, v3);
            }
        }
    }
}

// ---------------------------------------------------------------------------
// Combine: out = x + w0*(y0 + b2[e0]) + w1*(y1 + b2[e1])
// ---------------------------------------------------------------------------
__global__ void __launch_bounds__(256) k_combine(
    const float* __restrict__ x, const float* __restrict__ b2, float* __restrict__ out)
{
    const int t = blockIdx.x;
    const int r0 = g_slot_row[t * 2 + 0], r1 = g_slot_row[t * 2 + 1];
    const int e0 = g_slot_e[t * 2 + 0],  e1 = g_slot_e[t * 2 + 1];
    const float w0 = g_slot_w[t * 2 + 0], w1 = g_slot_w[t * 2 + 1];
    const float* y0 = g_y + (long long)r0 * HH;
    const float* y1 = g_y + (long long)r1 * HH;
    const float* bb0 = b2 + (long long)e0 * HH;
    const float* bb1 = b2 + (long long)e1 * HH;
    const float* xr = x + (long long)t * HH;
    float* o = out + (long long)t * HH;
    const int c = threadIdx.x * 4;
    float4 xv = *(const float4*)(xr + c);
    float4 a0 = *(const float4*)(y0 + c);
    float4 a1 = *(const float4*)(y1 + c);
    float4 c0 = *(const float4*)(bb0 + c);
    float4 c1 = *(const float4*)(bb1 + c);
    float4 r;
    r.x = xv.x + w0 * (a0.x + c0.x) + w1 * (a1.x + c1.x);
    r.y = xv.y + w0 * (a0.y + c0.y) + w1 * (a1.y + c1.y);
    r.z = xv.z + w0 * (a0.z + c0.z) + w1 * (a1.z + c1.z);
    r.w = xv.w + w0 * (a0.w + c0.w) + w1 * (a1.w + c1.w);
    *(float4*)(o + c) = r;
}

// ---------------------------------------------------------------------------
// Launch
// ---------------------------------------------------------------------------
extern "C" void kernel_launch(void* const* d_in, const int* in_sizes, int n_in,
                              void* d_out, int out_size)
{
    const float* x   = (const float*)d_in[0];
    const float* rW  = (const float*)d_in[1];
    const float* rb  = (const float*)d_in[2];
    const float* lng = (const float*)d_in[3];
    const float* lnb = (const float*)d_in[4];
    const float* W1  = (const float*)d_in[5];
    const float* b1  = (const float*)d_in[6];
    const float* W2  = (const float*)d_in[7];
    const float* b2  = (const float*)d_in[8];
    float* out = (float*)d_out;

    cudaFuncSetAttribute(k_gemm_h<true>,  cudaFuncAttributeMaxDynamicSharedMemorySize, GEMM_SMEM_BYTES);
    cudaFuncSetAttribute(k_gemm_h<false>, cudaFuncAttributeMaxDynamicSharedMemorySize, GEMM_SMEM_BYTES);

    __half* w1h; cudaGetSymbolAddress((void**)&w1h, g_W1h);
    __half* w2h; cudaGetSymbolAddress((void**)&w2h, g_W2h);

    k_f2h<<<2048, 256>>>(W1, w1h, W1N);
    k_f2h<<<2048, 256>>>(W2, w2h, W2N);

    k_zero<<<1, 32>>>();
    k_router_ln<<<TT, 256>>>(x, rW, rb);
    k_prefix<<<1, 32>>>();
    k_build_h<<<RTOT, 256>>>(x, lng, lnb);

    dim3 g1(FFD / 128, RTOT / 128, EE);   // 32 x 64 x 8 (most m-tiles exit early)
    k_gemm_h<true><<<g1, 256, GEMM_SMEM_BYTES>>>(w1h, b1);

    dim3 g2(HH / 128, RTOT / 128, EE);    // 8 x 64 x 8
    k_gemm_h<false><<<g2, 256, GEMM_SMEM_BYTES>>>(w2h, nullptr);

    k_combine<<<TT, 256>>>(x, b2, out);
}